// round 2
// baseline (speedup 1.0000x reference)
#include <cuda_runtime.h>
#include <cuda_bf16.h>

// Shower accumulator table, packed so the gather phase does ONE 16B L2 read
// per hit instead of four 4B reads.
//   x = e_track_shower (raw)     y = e_track_shower_corr
//   z = e_hit_shower   (raw)     w = e_hit_shower_corr
#define MAX_SEG 16384
__device__ float4 g_shower[MAX_SEG];

// ---------------------------------------------------------------------------
// Kernel 1: zero the accumulator table
// ---------------------------------------------------------------------------
__global__ void zero_kernel(int nseg) {
    int i = blockIdx.x * blockDim.x + threadIdx.x;
    if (i < nseg) g_shower[i] = make_float4(0.f, 0.f, 0.f, 0.f);
}

// ---------------------------------------------------------------------------
// Kernel 2: scatter — segment-sum energies into shower bins.
// 8 hits per thread. All loads front-batched (deep MLP window), then 8
// predicated global REDs. Noise hits (sid == -1) contribute exactly 0 in the
// reference, so they are skipped. recHitID==1 -> track (.x), ==0 -> hit (.z).
// ---------------------------------------------------------------------------
__global__ void __launch_bounds__(256) scatter8_kernel(
        const int* __restrict__ sid,
        const float* __restrict__ energy,
        const int* __restrict__ rid,
        int n) {
    int t = blockIdx.x * blockDim.x + threadIdx.x;
    long base = (long)t * 8;
    if (base + 8 <= n) {
        int4   s0 = __ldg((const int4*)(sid)    + 2*t);
        int4   s1 = __ldg((const int4*)(sid)    + 2*t + 1);
        float4 e0 = __ldg((const float4*)(energy) + 2*t);
        float4 e1 = __ldg((const float4*)(energy) + 2*t + 1);
        int4   r0 = __ldg((const int4*)(rid)    + 2*t);
        int4   r1 = __ldg((const int4*)(rid)    + 2*t + 1);
        int   s[8] = {s0.x, s0.y, s0.z, s0.w, s1.x, s1.y, s1.z, s1.w};
        float e[8] = {e0.x, e0.y, e0.z, e0.w, e1.x, e1.y, e1.z, e1.w};
        int   r[8] = {r0.x, r0.y, r0.z, r0.w, r1.x, r1.y, r1.z, r1.w};
#pragma unroll
        for (int k = 0; k < 8; k++) {
            if (s[k] >= 0) {
                float* p = reinterpret_cast<float*>(&g_shower[s[k] + 1]);
                // track -> offset 0 (.x), hit -> offset 2 (.z)
                atomicAdd(p + ((1 - r[k]) << 1), e[k]);
            }
        }
    } else if (base < n) {
        for (long i = base; i < n; i++) {
            int sv = sid[i];
            if (sv >= 0) {
                float* p = reinterpret_cast<float*>(&g_shower[sv + 1]);
                atomicAdd(p + ((1 - rid[i]) << 1), energy[i]);
            }
        }
    }
}

// ---------------------------------------------------------------------------
// Kernel 3: per-shower correction factors.
// corr[s] (s>=1) = pcf_ext[alpha_idx[s-1]] where pcf_ext[j] = pcf[j] if
// j < n_hits and sid[j] != -1, else 0 (covers both the noise zeroing and the
// appended zero row at index n_hits). corr[0] = 0.
// ---------------------------------------------------------------------------
__global__ void corr_kernel(const int* __restrict__ sid,
                            const float* __restrict__ pcf,
                            const int* __restrict__ a_tracks,
                            const int* __restrict__ a_hits,
                            int n_hits, int nseg) {
    int s = blockIdx.x * blockDim.x + threadIdx.x;
    if (s >= nseg) return;
    float ct = 0.f, ch = 0.f;
    if (s > 0) {
        int jt = a_tracks[s - 1];
        if (jt >= 0 && jt < n_hits && __ldg(sid + jt) != -1) ct = __ldg(pcf + jt);
        int jh = a_hits[s - 1];
        if (jh >= 0 && jh < n_hits && __ldg(sid + jh) != -1) ch = __ldg(pcf + jh);
    }
    float4 v = g_shower[s];
    g_shower[s].y = v.x * ct;   // track corrected
    g_shower[s].w = v.z * ch;   // hit corrected
}

// ---------------------------------------------------------------------------
// Kernel 4: gather — 8 hits per thread: 2 int4 sid loads, then 8 independent
// 16B L2 table gathers in flight, then 8 coalesced float4 stores.
// Output layout (reference tuple order):
//   [0,n)   e_track_raw   [n,2n)  e_track_corrected
//   [2n,3n) e_hit_raw     [3n,4n) e_hit_corrected
// ---------------------------------------------------------------------------
__global__ void __launch_bounds__(256) gather8_kernel(
        const int* __restrict__ sid,
        float* __restrict__ out,
        int n) {
    int t = blockIdx.x * blockDim.x + threadIdx.x;
    if ((long)t * 8 >= n) return;
    int4 a = __ldg((const int4*)(sid) + 2*t);
    int4 b = __ldg((const int4*)(sid) + 2*t + 1);
    float4 v0 = g_shower[a.x + 1];
    float4 v1 = g_shower[a.y + 1];
    float4 v2 = g_shower[a.z + 1];
    float4 v3 = g_shower[a.w + 1];
    float4 v4 = g_shower[b.x + 1];
    float4 v5 = g_shower[b.y + 1];
    float4 v6 = g_shower[b.z + 1];
    float4 v7 = g_shower[b.w + 1];

    float4* o = (float4*)out;
    long q = 2l * t;
    long s = (long)n / 4;          // float4 stride per output stream
    o[q]         = make_float4(v0.x, v1.x, v2.x, v3.x);   // track raw
    o[q + 1]     = make_float4(v4.x, v5.x, v6.x, v7.x);
    o[q + s]     = make_float4(v0.y, v1.y, v2.y, v3.y);   // track corrected
    o[q + s + 1] = make_float4(v4.y, v5.y, v6.y, v7.y);
    o[q + 2*s]     = make_float4(v0.z, v1.z, v2.z, v3.z); // hit raw
    o[q + 2*s + 1] = make_float4(v4.z, v5.z, v6.z, v7.z);
    o[q + 3*s]     = make_float4(v0.w, v1.w, v2.w, v3.w); // hit corrected
    o[q + 3*s + 1] = make_float4(v4.w, v5.w, v6.w, v7.w);
}

__global__ void gather_kernel_scalar(const int* __restrict__ sid,
                                     float* __restrict__ out,
                                     int n) {
    int i = blockIdx.x * blockDim.x + threadIdx.x;
    if (i >= n) return;
    float4 v = g_shower[sid[i] + 1];
    out[i]          = v.x;
    out[i + 1ll*n]  = v.y;
    out[i + 2ll*n]  = v.z;
    out[i + 3ll*n]  = v.w;
}

extern "C" void kernel_launch(void* const* d_in, const int* in_sizes, int n_in,
                              void* d_out, int out_size) {
    const int*   pred_sid = (const int*)  d_in[0];
    const float* pcf      = (const float*)d_in[1];
    const float* energy   = (const float*)d_in[2];
    const int*   rid      = (const int*)  d_in[3];
    // d_in[4] = pred_beta (unused)
    const int*   a_tracks = (const int*)  d_in[5];
    const int*   a_hits   = (const int*)  d_in[6];
    float*       out      = (float*)d_out;

    int n_hits    = in_sizes[0];
    int n_showers = in_sizes[5];
    int nseg      = n_showers + 1;
    if (nseg > MAX_SEG) nseg = MAX_SEG;

    const int TPB = 256;

    zero_kernel<<<(nseg + TPB - 1) / TPB, TPB>>>(nseg);

    int n8 = (n_hits + 7) / 8;
    scatter8_kernel<<<(n8 + TPB - 1) / TPB, TPB>>>(pred_sid, energy, rid, n_hits);

    corr_kernel<<<(nseg + TPB - 1) / TPB, TPB>>>(pred_sid, pcf, a_tracks, a_hits,
                                                 n_hits, nseg);

    if ((n_hits & 7) == 0) {
        gather8_kernel<<<(n8 + TPB - 1) / TPB, TPB>>>(pred_sid, out, n_hits);
    } else {
        gather_kernel_scalar<<<(n_hits + TPB - 1) / TPB, TPB>>>(pred_sid, out, n_hits);
    }
}

// round 3
// speedup vs baseline: 1.0758x; 1.0758x over previous
#include <cuda_runtime.h>
#include <cuda_bf16.h>

// Shower accumulator table, packed so the gather phase does ONE 16B read
// per hit.
//   x = e_track_shower (raw)     y = e_track_shower_corr
//   z = e_hit_shower   (raw)     w = e_hit_shower_corr
#define MAX_SEG 16384
__device__ float4 g_shower[MAX_SEG];

// ---------------------------------------------------------------------------
// Kernel 1: zero the accumulator table
// ---------------------------------------------------------------------------
__global__ void zero_kernel(int nseg) {
    int i = blockIdx.x * blockDim.x + threadIdx.x;
    if (i < nseg) g_shower[i] = make_float4(0.f, 0.f, 0.f, 0.f);
}

// ---------------------------------------------------------------------------
// Kernel 2: scatter — segment-sum energies into shower bins.
// 8 hits per thread, loads front-batched, then 8 predicated global REDs.
// Noise hits (sid == -1) contribute exactly 0 in the reference -> skipped.
// recHitID==1 -> track (.x), ==0 -> hit (.z).
// ---------------------------------------------------------------------------
__global__ void __launch_bounds__(256) scatter8_kernel(
        const int* __restrict__ sid,
        const float* __restrict__ energy,
        const int* __restrict__ rid,
        int n) {
    int t = blockIdx.x * blockDim.x + threadIdx.x;
    long base = (long)t * 8;
    if (base + 8 <= n) {
        int4   s0 = __ldg((const int4*)(sid)      + 2*t);
        int4   s1 = __ldg((const int4*)(sid)      + 2*t + 1);
        float4 e0 = __ldg((const float4*)(energy) + 2*t);
        float4 e1 = __ldg((const float4*)(energy) + 2*t + 1);
        int4   r0 = __ldg((const int4*)(rid)      + 2*t);
        int4   r1 = __ldg((const int4*)(rid)      + 2*t + 1);
        int   s[8] = {s0.x, s0.y, s0.z, s0.w, s1.x, s1.y, s1.z, s1.w};
        float e[8] = {e0.x, e0.y, e0.z, e0.w, e1.x, e1.y, e1.z, e1.w};
        int   r[8] = {r0.x, r0.y, r0.z, r0.w, r1.x, r1.y, r1.z, r1.w};
#pragma unroll
        for (int k = 0; k < 8; k++) {
            if (s[k] >= 0) {
                float* p = reinterpret_cast<float*>(&g_shower[s[k] + 1]);
                atomicAdd(p + ((1 - r[k]) << 1), e[k]);
            }
        }
    } else if (base < n) {
        for (long i = base; i < n; i++) {
            int sv = sid[i];
            if (sv >= 0) {
                float* p = reinterpret_cast<float*>(&g_shower[sv + 1]);
                atomicAdd(p + ((1 - rid[i]) << 1), energy[i]);
            }
        }
    }
}

// ---------------------------------------------------------------------------
// Kernel 3: per-shower correction factors.
// corr[s] (s>=1) = pcf_ext[alpha_idx[s-1]], where pcf_ext[j] = pcf[j] if
// j < n_hits and sid[j] != -1, else 0. corr[0] = 0.
// ---------------------------------------------------------------------------
__global__ void corr_kernel(const int* __restrict__ sid,
                            const float* __restrict__ pcf,
                            const int* __restrict__ a_tracks,
                            const int* __restrict__ a_hits,
                            int n_hits, int nseg) {
    int s = blockIdx.x * blockDim.x + threadIdx.x;
    if (s >= nseg) return;
    float ct = 0.f, ch = 0.f;
    if (s > 0) {
        int jt = a_tracks[s - 1];
        if (jt >= 0 && jt < n_hits && __ldg(sid + jt) != -1) ct = __ldg(pcf + jt);
        int jh = a_hits[s - 1];
        if (jh >= 0 && jh < n_hits && __ldg(sid + jh) != -1) ch = __ldg(pcf + jh);
    }
    float4 v = g_shower[s];
    g_shower[s].y = v.x * ct;   // track corrected
    g_shower[s].w = v.z * ch;   // hit corrected
}

// ---------------------------------------------------------------------------
// Kernel 4: gather — persistent CTAs. Each CTA caches the full float4 shower
// table in SHARED memory (avoids the L1tex wavefront-replay path of random
// global gathers), then streams hits: 1 int4 sid load -> 4 random LDS.128
// (bank-conflict cost only) -> 4 coalesced float4 stores.
// Output layout (reference tuple order):
//   [0,n)   e_track_raw   [n,2n)  e_track_corrected
//   [2n,3n) e_hit_raw     [3n,4n) e_hit_corrected
// ---------------------------------------------------------------------------
__global__ void __launch_bounds__(1024, 1) gather_smem_kernel(
        const int* __restrict__ sid,
        float* __restrict__ out,
        int n, int nseg) {
    extern __shared__ float4 tab[];
    for (int i = threadIdx.x; i < nseg; i += blockDim.x)
        tab[i] = g_shower[i];
    __syncthreads();

    long nquads = (long)n / 4;           // n divisible by 4 on this path
    long stride = (long)gridDim.x * blockDim.x;
    long s = nquads;                     // float4 stride per output stream
    float4* o = (float4*)out;

    for (long q = (long)blockIdx.x * blockDim.x + threadIdx.x; q < nquads;
         q += stride) {
        int4 a = __ldg((const int4*)(sid) + q);
        float4 v0 = tab[a.x + 1];
        float4 v1 = tab[a.y + 1];
        float4 v2 = tab[a.z + 1];
        float4 v3 = tab[a.w + 1];
        o[q]         = make_float4(v0.x, v1.x, v2.x, v3.x);  // track raw
        o[q + s]     = make_float4(v0.y, v1.y, v2.y, v3.y);  // track corrected
        o[q + 2*s]   = make_float4(v0.z, v1.z, v2.z, v3.z);  // hit raw
        o[q + 3*s]   = make_float4(v0.w, v1.w, v2.w, v3.w);  // hit corrected
    }
}

__global__ void gather_kernel_scalar(const int* __restrict__ sid,
                                     float* __restrict__ out,
                                     int n) {
    int i = blockIdx.x * blockDim.x + threadIdx.x;
    if (i >= n) return;
    float4 v = g_shower[sid[i] + 1];
    out[i]          = v.x;
    out[i + 1ll*n]  = v.y;
    out[i + 2ll*n]  = v.z;
    out[i + 3ll*n]  = v.w;
}

extern "C" void kernel_launch(void* const* d_in, const int* in_sizes, int n_in,
                              void* d_out, int out_size) {
    const int*   pred_sid = (const int*)  d_in[0];
    const float* pcf      = (const float*)d_in[1];
    const float* energy   = (const float*)d_in[2];
    const int*   rid      = (const int*)  d_in[3];
    // d_in[4] = pred_beta (unused)
    const int*   a_tracks = (const int*)  d_in[5];
    const int*   a_hits   = (const int*)  d_in[6];
    float*       out      = (float*)d_out;

    int n_hits    = in_sizes[0];
    int n_showers = in_sizes[5];
    int nseg      = n_showers + 1;
    if (nseg > MAX_SEG) nseg = MAX_SEG;

    // One-time setup (host-only, done on the pre-capture correctness call):
    // SM count for the persistent gather grid + raised dynamic smem limit.
    static int sm_count = 0;
    static bool smem_ok = false;
    if (sm_count == 0) {
        cudaDeviceProp prop;
        cudaGetDeviceProperties(&prop, 0);
        sm_count = prop.multiProcessorCount;
        if (sm_count <= 0) sm_count = 148;
        smem_ok = (cudaFuncSetAttribute(
                       gather_smem_kernel,
                       cudaFuncAttributeMaxDynamicSharedMemorySize,
                       MAX_SEG * (int)sizeof(float4)) == cudaSuccess);
    }

    const int TPB = 256;

    zero_kernel<<<(nseg + TPB - 1) / TPB, TPB>>>(nseg);

    int n8 = (n_hits + 7) / 8;
    scatter8_kernel<<<(n8 + TPB - 1) / TPB, TPB>>>(pred_sid, energy, rid, n_hits);

    corr_kernel<<<(nseg + TPB - 1) / TPB, TPB>>>(pred_sid, pcf, a_tracks, a_hits,
                                                 n_hits, nseg);

    size_t smem_bytes = (size_t)nseg * sizeof(float4);
    if ((n_hits & 3) == 0 && smem_ok && smem_bytes <= 160 * 1024) {
        gather_smem_kernel<<<sm_count, 1024, smem_bytes>>>(pred_sid, out,
                                                           n_hits, nseg);
    } else {
        gather_kernel_scalar<<<(n_hits + TPB - 1) / TPB, TPB>>>(pred_sid, out,
                                                                n_hits);
    }
}